// round 16
// baseline (speedup 1.0000x reference)
#include <cuda_runtime.h>
#include <cuda_fp16.h>
#include <cstdint>
#include <math.h>

// ---------------------------------------------------------------------------
// Problem constants
// ---------------------------------------------------------------------------
#define T_SEQ    3072
#define DIM      2048
#define N_HEADS  16
#define Q_LORA   1536
#define KV_LORA  512
#define NOPE     128
#define ROPE     64
#define V_DIM    128
#define HD       (NOPE + ROPE)       // 192
#define EPS      1e-6f
#define KVD_PAD  640
#define QCAT     (N_HEADS * NOPE + N_HEADS * ROPE)   // 3072

__device__ __forceinline__ uint32_t smem_u32(const void* p) {
    uint32_t a;
    asm("{ .reg .u64 t; cvta.to.shared.u64 t, %1; cvt.u32.u64 %0, t; }" : "=r"(a) : "l"(p));
    return a;
}
__device__ __forceinline__ void cp_async16(uint32_t saddr, const void* gptr) {
    asm volatile("cp.async.cg.shared.global [%0], [%1], 16;" :: "r"(saddr), "l"(gptr));
}
#define CP_COMMIT() asm volatile("cp.async.commit_group;")
#define CP_WAIT(n)  asm volatile("cp.async.wait_group %0;" :: "n"(n))

#define MMA_F16(d0,d1,d2,d3,a0,a1,a2,a3,b0,b1) \
    asm volatile( \
        "mma.sync.aligned.m16n8k16.row.col.f32.f16.f16.f32 " \
        "{%0,%1,%2,%3}, {%4,%5,%6,%7}, {%8,%9}, {%0,%1,%2,%3};" \
        : "+f"(d0), "+f"(d1), "+f"(d2), "+f"(d3) \
        : "r"(a0), "r"(a1), "r"(a2), "r"(a3), "r"(b0), "r"(b1))

#define LDSM_X4(r0,r1,r2,r3,addr) \
    asm volatile("ldmatrix.sync.aligned.m8n8.x4.shared.b16 {%0,%1,%2,%3}, [%4];" \
        : "=r"(r0), "=r"(r1), "=r"(r2), "=r"(r3) : "r"(addr))

__device__ __forceinline__ uint32_t packh2(float a, float b) {
    __half2 t = __floats2half2_rn(a, b);
    return *(uint32_t*)&t;
}

// ---------------------------------------------------------------------------
// Scratch (static device globals)
// ---------------------------------------------------------------------------
__device__ float  g_qdt  [T_SEQ * Q_LORA];
__device__ float  g_qcat [T_SEQ * QCAT];
__device__ float  g_kvd  [T_SEQ * KVD_PAD];
__device__ float  g_kvup [T_SEQ * N_HEADS * (NOPE + V_DIM)];

// fp16 operands
__device__ __half g_x16 [T_SEQ * DIM];
__device__ __half g_ql16[T_SEQ * Q_LORA];
__device__ __half g_ck16[T_SEQ * KV_LORA];
__device__ __half g_of16[T_SEQ * N_HEADS * V_DIM];
__device__ __half g_qh  [T_SEQ * N_HEADS * HD];
__device__ __half g_kh  [T_SEQ * N_HEADS * HD];
__device__ __half g_vt  [N_HEADS * V_DIM * T_SEQ];

// fp16 transposed (K-major [N][K]) weights
__device__ __half g_wqdT[Q_LORA * DIM];
__device__ __half g_wqT [QCAT * Q_LORA];
__device__ __half g_wkdT[KVD_PAD * DIM];
__device__ __half g_wkuT[(N_HEADS * (NOPE + V_DIM)) * KV_LORA];
__device__ __half g_woT [DIM * (N_HEADS * V_DIM)];

// ---------------------------------------------------------------------------
// fp32 -> fp16 convert (vectorized)
// ---------------------------------------------------------------------------
__global__ __launch_bounds__(256)
void convert_f16(const float* __restrict__ src, __half* __restrict__ dst, int n4) {
    int i = blockIdx.x * 256 + threadIdx.x;
    if (i < n4) {
        float4 v = *(const float4*)&src[i * 4];
        __half2* d = (__half2*)dst;
        d[i * 2]     = __floats2half2_rn(v.x, v.y);
        d[i * 2 + 1] = __floats2half2_rn(v.z, v.w);
    }
}

// ---------------------------------------------------------------------------
// Weight transpose: src[K][N] -> dst[NP][K] fp16, zero pad
// ---------------------------------------------------------------------------
__global__ __launch_bounds__(256)
void transpose_f16(const float* __restrict__ src, __half* __restrict__ dst,
                   int K, int N, int NP) {
    __shared__ float tile[32][33];
    int kb = blockIdx.y * 32, nb = blockIdx.x * 32;
    for (int i = threadIdx.y; i < 32; i += 8) {
        int n = nb + threadIdx.x;
        float v = (n < N) ? src[(size_t)(kb + i) * N + n] : 0.f;
        tile[i][threadIdx.x] = v;
    }
    __syncthreads();
    for (int i = threadIdx.y; i < 32; i += 8) {
        int n = nb + i;
        if (n < NP)
            dst[(size_t)n * K + kb + threadIdx.x] = __float2half_rn(tile[threadIdx.x][i]);
    }
}

// ---------------------------------------------------------------------------
// FP16 mma.sync GEMM (R12-exact, best measured)
// ---------------------------------------------------------------------------
#define HSMS 40
#define STAGES 3
#define HTILE (128 * HSMS)
#define GEMM_SMEM (STAGES * 2 * HTILE * 2)

__global__ __launch_bounds__(128)
void mma_gemm_f16(const __half* __restrict__ A, const __half* __restrict__ Bt,
                  float* __restrict__ C, int M, int N, int K) {
    extern __shared__ __half shh[];
    __half* AsAll = shh;
    __half* BsAll = shh + STAGES * HTILE;
    const uint32_t as_base = smem_u32(AsAll);
    const uint32_t bs_base = smem_u32(BsAll);

    const int tid  = threadIdx.x;
    const int wid  = tid >> 5, lane = tid & 31;
    const int gid  = lane >> 2, tig = lane & 3;
    const int wm   = wid >> 1, wn = wid & 1;
    const int bm   = blockIdx.y, bn = blockIdx.x;

    const __half* Ab = A  + (size_t)bm * 128 * K;
    const __half* Bb = Bt + (size_t)bn * 128 * K;

    const int lrow = tid >> 2;
    const int lc4  = tid & 3;

    float acc[4][8][4];
    #pragma unroll
    for (int i = 0; i < 4; i++)
        #pragma unroll
        for (int j = 0; j < 8; j++)
            #pragma unroll
            for (int k = 0; k < 4; k++) acc[i][j][k] = 0.f;

    const int nk = K >> 5;

    #pragma unroll
    for (int s = 0; s < STAGES - 1; s++) {
        const int k0 = s * 32;
        #pragma unroll
        for (int l = 0; l < 4; l++) {
            int row = lrow + l * 32;
            uint32_t soff = (uint32_t)(s * HTILE + row * HSMS) * 2 + lc4 * 16;
            cp_async16(as_base + soff, Ab + (size_t)row * K + k0 + lc4 * 8);
            cp_async16(bs_base + soff, Bb + (size_t)row * K + k0 + lc4 * 8);
        }
        CP_COMMIT();
    }

    for (int kt = 0; kt < nk; kt++) {
        CP_WAIT(STAGES - 2);
        __syncthreads();

        if (kt + STAGES - 1 < nk) {
            const int s = (kt + STAGES - 1) % STAGES;
            const int k0 = (kt + STAGES - 1) * 32;
            #pragma unroll
            for (int l = 0; l < 4; l++) {
                int row = lrow + l * 32;
                uint32_t soff = (uint32_t)(s * HTILE + row * HSMS) * 2 + lc4 * 16;
                cp_async16(as_base + soff, Ab + (size_t)row * K + k0 + lc4 * 8);
                cp_async16(bs_base + soff, Bb + (size_t)row * K + k0 + lc4 * 8);
            }
        }
        CP_COMMIT();

        const uint32_t* as = (const uint32_t*)(AsAll + (kt % STAGES) * HTILE);
        const uint32_t* bs = (const uint32_t*)(BsAll + (kt % STAGES) * HTILE);
        #pragma unroll
        for (int kc = 0; kc < 2; kc++) {
            const int kw = kc * 8 + tig;
            uint32_t a[4][4], b[8][2];
            #pragma unroll
            for (int mf = 0; mf < 4; mf++) {
                int row = wm * 64 + mf * 16 + gid;
                a[mf][0] = as[row * 20 + kw];
                a[mf][1] = as[(row + 8) * 20 + kw];
                a[mf][2] = as[row * 20 + kw + 4];
                a[mf][3] = as[(row + 8) * 20 + kw + 4];
            }
            #pragma unroll
            for (int nf = 0; nf < 8; nf++) {
                int col = wn * 64 + nf * 8 + gid;
                b[nf][0] = bs[col * 20 + kw];
                b[nf][1] = bs[col * 20 + kw + 4];
            }
            #pragma unroll
            for (int mf = 0; mf < 4; mf++)
                #pragma unroll
                for (int nf = 0; nf < 8; nf++)
                    MMA_F16(acc[mf][nf][0], acc[mf][nf][1], acc[mf][nf][2], acc[mf][nf][3],
                            a[mf][0], a[mf][1], a[mf][2], a[mf][3],
                            b[nf][0], b[nf][1]);
        }
    }

    #pragma unroll
    for (int mf = 0; mf < 4; mf++) {
        int row0 = bm * 128 + wm * 64 + mf * 16 + gid;
        #pragma unroll
        for (int nf = 0; nf < 8; nf++) {
            int col = bn * 128 + wn * 64 + nf * 8 + tig * 2;
            *(float2*)&C[(size_t)row0 * N + col]       = make_float2(acc[mf][nf][0], acc[mf][nf][1]);
            *(float2*)&C[(size_t)(row0 + 8) * N + col] = make_float2(acc[mf][nf][2], acc[mf][nf][3]);
        }
    }
}

// ---------------------------------------------------------------------------
// Row-wise RMSNorm, fp16 output
// ---------------------------------------------------------------------------
__global__ __launch_bounds__(256)
void rmsnorm_f16(const float* __restrict__ in, const float* __restrict__ w,
                 __half* __restrict__ out, int instride, int outstride, int cols) {
    int r = blockIdx.x;
    const float* row = in + (size_t)r * instride;
    float ss = 0.f;
    for (int c = threadIdx.x; c < cols; c += blockDim.x) {
        float v = row[c];
        ss += v * v;
    }
    __shared__ float red[8];
    int lane = threadIdx.x & 31, wid = threadIdx.x >> 5;
    #pragma unroll
    for (int o = 16; o; o >>= 1) ss += __shfl_xor_sync(0xFFFFFFFFu, ss, o);
    if (lane == 0) red[wid] = ss;
    __syncthreads();
    if (wid == 0) {
        float v = (lane < 8) ? red[lane] : 0.f;
        #pragma unroll
        for (int o = 4; o; o >>= 1) v += __shfl_xor_sync(0xFFFFFFFFu, v, o);
        if (lane == 0) red[0] = v;
    }
    __syncthreads();
    float inv = rsqrtf(red[0] / (float)cols + EPS);
    __half* orow = out + (size_t)r * outstride;
    for (int c = threadIdx.x; c < cols; c += blockDim.x)
        orow[c] = __float2half_rn(row[c] * inv * w[c]);
}

// ---------------------------------------------------------------------------
// Assemble Q -> fp16 g_qh from concatenated q projection
// ---------------------------------------------------------------------------
__global__ __launch_bounds__(256)
void assemble_q(const float* __restrict__ freqs) {
    int t = blockIdx.x;
    int tid = threadIdx.x;
    for (int i = tid; i < 512; i += 256) {
        int e = i * 4;
        int h = e >> 7, d = e & 127;
        float4 v = *(const float4*)&g_qcat[(size_t)t * QCAT + e];
        __half* dst = &g_qh[((size_t)t * N_HEADS + h) * HD + d];
        *(__half2*)&dst[0] = __floats2half2_rn(v.x, v.y);
        *(__half2*)&dst[2] = __floats2half2_rn(v.z, v.w);
    }
    for (int i = tid; i < N_HEADS * 32; i += 256) {
        int h = i >> 5, p = i & 31;
        float f = freqs[t * 32 + p];
        float c = cosf(f), s = sinf(f);
        const float* src = &g_qcat[(size_t)t * QCAT + N_HEADS * NOPE + h * ROPE + 2 * p];
        float x1 = src[0], x2 = src[1];
        __half* dst = &g_qh[((size_t)t * N_HEADS + h) * HD + NOPE + 2 * p];
        *(__half2*)dst = __floats2half2_rn(x1 * c - x2 * s, x1 * s + x2 * c);
    }
}

// ---------------------------------------------------------------------------
// Assemble K -> fp16 g_kh
// ---------------------------------------------------------------------------
__global__ __launch_bounds__(256)
void assemble_k(const float* __restrict__ freqs) {
    int t = blockIdx.x;
    int tid = threadIdx.x;
    for (int i = tid; i < 512; i += 256) {
        int e = i * 4;
        int h = e >> 7, d = e & 127;
        float4 v = *(const float4*)&g_kvup[(size_t)t * (N_HEADS * (NOPE + V_DIM)) + h * (NOPE + V_DIM) + d];
        __half* dst = &g_kh[((size_t)t * N_HEADS + h) * HD + d];
        *(__half2*)&dst[0] = __floats2half2_rn(v.x, v.y);
        *(__half2*)&dst[2] = __floats2half2_rn(v.z, v.w);
    }
    __shared__ __half2 rk[32];
    if (tid < 32) {
        float f = freqs[t * 32 + tid];
        float c = cosf(f), s = sinf(f);
        const float* src = &g_kvd[(size_t)t * KVD_PAD + KV_LORA + 2 * tid];
        float x1 = src[0], x2 = src[1];
        rk[tid] = __floats2half2_rn(x1 * c - x2 * s, x1 * s + x2 * c);
    }
    __syncthreads();
    for (int i = tid; i < N_HEADS * 32; i += 256) {
        int h = i >> 5, p = i & 31;
        *(__half2*)&g_kh[((size_t)t * N_HEADS + h) * HD + NOPE + 2 * p] = rk[p];
    }
}

// ---------------------------------------------------------------------------
// V transpose: g_kvup V-part -> g_vt[h][d][t] fp16
// ---------------------------------------------------------------------------
__global__ __launch_bounds__(256)
void transpose_v() {
    __shared__ __half tile[32][33];
    int h = blockIdx.z;
    int t0 = blockIdx.x * 32, d0 = blockIdx.y * 32;
    for (int i = threadIdx.y; i < 32; i += 8) {
        int t = t0 + i, d = d0 + threadIdx.x;
        tile[i][threadIdx.x] = __float2half_rn(
            g_kvup[(size_t)t * (N_HEADS * (NOPE + V_DIM)) + h * (NOPE + V_DIM) + NOPE + d]);
    }
    __syncthreads();
    for (int i = threadIdx.y; i < 32; i += 8) {
        int d = d0 + i;
        g_vt[((size_t)h * V_DIM + d) * T_SEQ + t0 + threadIdx.x] = tile[threadIdx.x][i];
    }
}

// ---------------------------------------------------------------------------
// FlashAttention-2 causal attention.
// R16: Q fragments hoisted to registers; K/V B-operands via ldmatrix.x4
// (fixed smem bases -> loop-invariant addresses + kc*32).
// ---------------------------------------------------------------------------
#define AQS 200
#define AVS 72
#define SMEM_FA ((64 * AQS + 64 * AQS + 128 * AVS) * 2)

__global__ __launch_bounds__(128)
void attn_fa2() {
    extern __shared__ __half smh[];
    __half* Qh = smh;
    __half* Kh = Qh + 64 * AQS;
    __half* Vt = Kh + 64 * AQS;
    const uint32_t* Qw = (const uint32_t*)Qh;
    const uint32_t kh_base = smem_u32(Kh);
    const uint32_t vt_base = smem_u32(Vt);

    const int h  = blockIdx.y;
    const int qt = blockIdx.x;
    const int tid = threadIdx.x;
    const int w = tid >> 5, lane = tid & 31;
    const int gid = lane >> 2, tig = lane & 3;
    const int l15 = lane & 15, l16 = lane >> 4;
    const int q0 = qt * 64;
    const float scale = 0.07216878364870323f;

    for (int i = tid; i < 1536; i += 128) {
        int r = i / 24, c = i % 24;
        *(uint4*)(Qh + r * AQS + c * 8) =
            *(const uint4*)(g_qh + ((size_t)(q0 + r) * N_HEADS + h) * HD + c * 8);
    }
    __syncthreads();

    // hoist Q fragments (loop-invariant; Q smem never overwritten)
    const int row0 = w * 16 + gid;
    uint32_t qa[12][4];
    #pragma unroll
    for (int kc = 0; kc < 12; kc++) {
        qa[kc][0] = Qw[row0 * 100 + kc * 8 + tig];
        qa[kc][1] = Qw[(row0 + 8) * 100 + kc * 8 + tig];
        qa[kc][2] = Qw[row0 * 100 + kc * 8 + tig + 4];
        qa[kc][3] = Qw[(row0 + 8) * 100 + kc * 8 + tig + 4];
    }

    // loop-invariant ldmatrix base addresses
    uint32_t kaddr[4], vaddr[8];
    #pragma unroll
    for (int p = 0; p < 4; p++)
        kaddr[p] = kh_base + (uint32_t)((p * 16 + l15) * (AQS * 2) + l16 * 16);
    #pragma unroll
    for (int p = 0; p < 8; p++)
        vaddr[p] = vt_base + (uint32_t)((p * 16 + l15) * (AVS * 2) + l16 * 16);

    float o[16][4];
    #pragma unroll
    for (int nf = 0; nf < 16; nf++) {
        o[nf][0] = 0.f; o[nf][1] = 0.f; o[nf][2] = 0.f; o[nf][3] = 0.f;
    }
    float m0 = -1e30f, m1 = -1e30f, l0 = 0.f, l1 = 0.f;

    const int ntiles = qt + 1;
    for (int kt = 0; kt < ntiles; kt++) {
        __syncthreads();
        for (int i = tid; i < 1536; i += 128) {
            int r = i / 24, c = i % 24;
            *(uint4*)(Kh + r * AQS + c * 8) =
                *(const uint4*)(g_kh + ((size_t)(kt * 64 + r) * N_HEADS + h) * HD + c * 8);
        }
        for (int i = tid; i < 1024; i += 128) {
            int d = i >> 3, c = i & 7;
            *(uint4*)(Vt + d * AVS + c * 8) =
                *(const uint4*)(g_vt + ((size_t)h * V_DIM + d) * T_SEQ + kt * 64 + c * 8);
        }
        __syncthreads();

        // S = Q K^T : K B-fragments via ldmatrix
        float s[8][4];
        #pragma unroll
        for (int nf = 0; nf < 8; nf++) {
            s[nf][0] = 0.f; s[nf][1] = 0.f; s[nf][2] = 0.f; s[nf][3] = 0.f;
        }
        #pragma unroll
        for (int kc = 0; kc < 12; kc++) {
            uint32_t b[8][2];
            #pragma unroll
            for (int p = 0; p < 4; p++) {
                uint32_t q0r, q1r, q2r, q3r;
                LDSM_X4(q0r, q1r, q2r, q3r, kaddr[p] + (uint32_t)(kc * 32));
                b[2 * p][0]     = q0r;
                b[2 * p + 1][0] = q1r;
                b[2 * p][1]     = q2r;
                b[2 * p + 1][1] = q3r;
            }
            #pragma unroll
            for (int nf = 0; nf < 8; nf++)
                MMA_F16(s[nf][0], s[nf][1], s[nf][2], s[nf][3],
                        qa[kc][0], qa[kc][1], qa[kc][2], qa[kc][3],
                        b[nf][0], b[nf][1]);
        }

        const int qg0 = q0 + row0, qg1 = qg0 + 8;
        #pragma unroll
        for (int nf = 0; nf < 8; nf++) {
            int jg = kt * 64 + nf * 8 + tig * 2;
            s[nf][0] = (jg     <= qg0) ? s[nf][0] * scale : -1e30f;
            s[nf][1] = (jg + 1 <= qg0) ? s[nf][1] * scale : -1e30f;
            s[nf][2] = (jg     <= qg1) ? s[nf][2] * scale : -1e30f;
            s[nf][3] = (jg + 1 <= qg1) ? s[nf][3] * scale : -1e30f;
        }

        float rm0 = -1e30f, rm1 = -1e30f;
        #pragma unroll
        for (int nf = 0; nf < 8; nf++) {
            rm0 = fmaxf(rm0, fmaxf(s[nf][0], s[nf][1]));
            rm1 = fmaxf(rm1, fmaxf(s[nf][2], s[nf][3]));
        }
        rm0 = fmaxf(rm0, __shfl_xor_sync(0xFFFFFFFFu, rm0, 1));
        rm0 = fmaxf(rm0, __shfl_xor_sync(0xFFFFFFFFu, rm0, 2));
        rm1 = fmaxf(rm1, __shfl_xor_sync(0xFFFFFFFFu, rm1, 1));
        rm1 = fmaxf(rm1, __shfl_xor_sync(0xFFFFFFFFu, rm1, 2));
        float nm0 = fmaxf(m0, rm0), nm1 = fmaxf(m1, rm1);
        float sc0 = __expf(m0 - nm0), sc1 = __expf(m1 - nm1);
        m0 = nm0; m1 = nm1;
        float rs0 = 0.f, rs1 = 0.f;
        #pragma unroll
        for (int nf = 0; nf < 8; nf++) {
            s[nf][0] = __expf(s[nf][0] - nm0); rs0 += s[nf][0];
            s[nf][1] = __expf(s[nf][1] - nm0); rs0 += s[nf][1];
            s[nf][2] = __expf(s[nf][2] - nm1); rs1 += s[nf][2];
            s[nf][3] = __expf(s[nf][3] - nm1); rs1 += s[nf][3];
        }
        rs0 += __shfl_xor_sync(0xFFFFFFFFu, rs0, 1);
        rs0 += __shfl_xor_sync(0xFFFFFFFFu, rs0, 2);
        rs1 += __shfl_xor_sync(0xFFFFFFFFu, rs1, 1);
        rs1 += __shfl_xor_sync(0xFFFFFFFFu, rs1, 2);
        l0 = l0 * sc0 + rs0;
        l1 = l1 * sc1 + rs1;
        #pragma unroll
        for (int nf = 0; nf < 16; nf++) {
            o[nf][0] *= sc0; o[nf][1] *= sc0;
            o[nf][2] *= sc1; o[nf][3] *= sc1;
        }

        // O += P V : V B-fragments via ldmatrix
        #pragma unroll
        for (int kc = 0; kc < 4; kc++) {
            uint32_t a0 = packh2(s[2 * kc][0],     s[2 * kc][1]);
            uint32_t a1 = packh2(s[2 * kc][2],     s[2 * kc][3]);
            uint32_t a2 = packh2(s[2 * kc + 1][0], s[2 * kc + 1][1]);
            uint32_t a3 = packh2(s[2 * kc + 1][2], s[2 * kc + 1][3]);
            uint32_t b[16][2];
            #pragma unroll
            for (int p = 0; p < 8; p++) {
                uint32_t q0r, q1r, q2r, q3r;
                LDSM_X4(q0r, q1r, q2r, q3r, vaddr[p] + (uint32_t)(kc * 32));
                b[2 * p][0]     = q0r;
                b[2 * p + 1][0] = q1r;
                b[2 * p][1]     = q2r;
                b[2 * p + 1][1] = q3r;
            }
            #pragma unroll
            for (int nf = 0; nf < 16; nf++)
                MMA_F16(o[nf][0], o[nf][1], o[nf][2], o[nf][3],
                        a0, a1, a2, a3, b[nf][0], b[nf][1]);
        }
    }

    float li0 = 1.f / l0, li1 = 1.f / l1;
    const int gr0 = q0 + row0, gr1 = gr0 + 8;
    #pragma unroll
    for (int nf = 0; nf < 16; nf++) {
        int col = nf * 8 + tig * 2;
        *(__half2*)&g_of16[(size_t)gr0 * (N_HEADS * V_DIM) + h * V_DIM + col] =
            __floats2half2_rn(o[nf][0] * li0, o[nf][1] * li0);
        *(__half2*)&g_of16[(size_t)gr1 * (N_HEADS * V_DIM) + h * V_DIM + col] =
            __floats2half2_rn(o[nf][2] * li1, o[nf][3] * li1);
    }
}

// ---------------------------------------------------------------------------
// Launcher (R15 dual-stream exact)
// ---------------------------------------------------------------------------
extern "C" void kernel_launch(void* const* d_in, const int* in_sizes, int n_in,
                              void* d_out, int out_size) {
    const float* x         = (const float*)d_in[0];
    const float* freqs     = (const float*)d_in[1];
    const float* wq_down   = (const float*)d_in[3];
    const float* q_norm_w  = (const float*)d_in[4];
    const float* wq_nope   = (const float*)d_in[5];
    const float* wq_rope   = (const float*)d_in[6];
    const float* wkv_down  = (const float*)d_in[7];
    const float* kv_norm_w = (const float*)d_in[8];
    const float* wkv_up    = (const float*)d_in[9];
    const float* wo        = (const float*)d_in[10];
    float* out = (float*)d_out;

    float *p_qdt, *p_qcat, *p_kvd, *p_kvup;
    __half *p_x16, *p_ql16, *p_ck16, *p_of16;
    __half *p_wqdT, *p_wqT, *p_wkdT, *p_wkuT, *p_woT;
    cudaGetSymbolAddress((void**)&p_qdt,   g_qdt);
    cudaGetSymbolAddress((void**)&p_qcat,  g_qcat);
    cudaGetSymbolAddress((void**)&p_kvd,   g_kvd);
    cudaGetSymbolAddress((void**)&p_kvup,  g_kvup);
    cudaGetSymbolAddress((void**)&p_x16,   g_x16);
    cudaGetSymbolAddress((void**)&p_ql16,  g_ql16);
    cudaGetSymbolAddress((void**)&p_ck16,  g_ck16);
    cudaGetSymbolAddress((void**)&p_of16,  g_of16);
    cudaGetSymbolAddress((void**)&p_wqdT,  g_wqdT);
    cudaGetSymbolAddress((void**)&p_wqT,   g_wqT);
    cudaGetSymbolAddress((void**)&p_wkdT,  g_wkdT);
    cudaGetSymbolAddress((void**)&p_wkuT,  g_wkuT);
    cudaGetSymbolAddress((void**)&p_woT,   g_woT);

    cudaFuncSetAttribute(mma_gemm_f16, cudaFuncAttributeMaxDynamicSharedMemorySize, GEMM_SMEM);
    cudaFuncSetAttribute(attn_fa2, cudaFuncAttributeMaxDynamicSharedMemorySize, SMEM_FA);

    static cudaStream_t s1 = nullptr;
    static cudaEvent_t  ev_x = nullptr, ev_kv = nullptr;
    if (!s1) {
        cudaStreamCreateWithFlags(&s1, cudaStreamNonBlocking);
        cudaEventCreateWithFlags(&ev_x,  cudaEventDisableTiming);
        cudaEventCreateWithFlags(&ev_kv, cudaEventDisableTiming);
    }
    cudaStream_t s0 = 0;

    const dim3 tb(32, 8);
    const int MB = T_SEQ / 128;   // 24

    convert_f16<<<(T_SEQ * DIM / 4 + 255) / 256, 256, 0, s0>>>(x, p_x16, T_SEQ * DIM / 4);
    cudaEventRecord(ev_x, s0);

    cudaStreamWaitEvent(s1, ev_x, 0);
    transpose_f16<<<dim3(KVD_PAD / 32, DIM / 32), tb, 0, s1>>>(wkv_down, p_wkdT, DIM, KV_LORA + ROPE, KVD_PAD);
    mma_gemm_f16<<<dim3(KVD_PAD / 128, MB), 128, GEMM_SMEM, s1>>>(p_x16, p_wkdT, p_kvd, T_SEQ, KVD_PAD, DIM);
    transpose_f16<<<dim3((N_HEADS*(NOPE+V_DIM)) / 32, KV_LORA / 32), tb, 0, s1>>>(wkv_up, p_wkuT, KV_LORA, N_HEADS*(NOPE+V_DIM), N_HEADS*(NOPE+V_DIM));
    rmsnorm_f16<<<T_SEQ, 256, 0, s1>>>(p_kvd, kv_norm_w, p_ck16, KVD_PAD, KV_LORA, KV_LORA);
    mma_gemm_f16<<<dim3((N_HEADS*(NOPE+V_DIM)) / 128, MB), 128, GEMM_SMEM, s1>>>(p_ck16, p_wkuT, p_kvup, T_SEQ, N_HEADS*(NOPE+V_DIM), KV_LORA);
    assemble_k<<<T_SEQ, 256, 0, s1>>>(freqs);
    transpose_v<<<dim3(T_SEQ / 32, V_DIM / 32, N_HEADS), tb, 0, s1>>>();
    cudaEventRecord(ev_kv, s1);

    transpose_f16<<<dim3(Q_LORA / 32, DIM / 32), tb, 0, s0>>>(wq_down, p_wqdT, DIM, Q_LORA, Q_LORA);
    mma_gemm_f16<<<dim3(Q_LORA / 128, MB), 128, GEMM_SMEM, s0>>>(p_x16, p_wqdT, p_qdt, T_SEQ, Q_LORA, DIM);
    transpose_f16<<<dim3((N_HEADS*NOPE) / 32, Q_LORA / 32), tb, 0, s0>>>(wq_nope, p_wqT, Q_LORA, N_HEADS*NOPE, N_HEADS*NOPE);
    transpose_f16<<<dim3((N_HEADS*ROPE) / 32, Q_LORA / 32), tb, 0, s0>>>(wq_rope, p_wqT + (size_t)(N_HEADS*NOPE) * Q_LORA, Q_LORA, N_HEADS*ROPE, N_HEADS*ROPE);
    transpose_f16<<<dim3(DIM / 32, (N_HEADS*V_DIM) / 32), tb, 0, s0>>>(wo, p_woT, N_HEADS*V_DIM, DIM, DIM);
    rmsnorm_f16<<<T_SEQ, 256, 0, s0>>>(p_qdt, q_norm_w, p_ql16, Q_LORA, Q_LORA, Q_LORA);
    mma_gemm_f16<<<dim3(QCAT / 128, MB), 128, GEMM_SMEM, s0>>>(p_ql16, p_wqT, p_qcat, T_SEQ, QCAT, Q_LORA);
    assemble_q<<<T_SEQ, 256, 0, s0>>>(freqs);

    cudaStreamWaitEvent(s0, ev_kv, 0);
    attn_fa2<<<dim3(T_SEQ / 64, N_HEADS), 128, SMEM_FA, s0>>>();
    mma_gemm_f16<<<dim3(DIM / 128, MB), 128, GEMM_SMEM, s0>>>(p_of16, p_woT, out, T_SEQ, DIM, DIM);
}

// round 17
// speedup vs baseline: 1.1166x; 1.1166x over previous
#include <cuda_runtime.h>
#include <cuda_fp16.h>
#include <cstdint>
#include <math.h>

// ---------------------------------------------------------------------------
// Problem constants
// ---------------------------------------------------------------------------
#define T_SEQ    3072
#define DIM      2048
#define N_HEADS  16
#define Q_LORA   1536
#define KV_LORA  512
#define NOPE     128
#define ROPE     64
#define V_DIM    128
#define HD       (NOPE + ROPE)       // 192
#define EPS      1e-6f
#define KVD_PAD  640
#define QCAT     (N_HEADS * NOPE + N_HEADS * ROPE)   // 3072

__device__ __forceinline__ uint32_t smem_u32(const void* p) {
    uint32_t a;
    asm("{ .reg .u64 t; cvta.to.shared.u64 t, %1; cvt.u32.u64 %0, t; }" : "=r"(a) : "l"(p));
    return a;
}
__device__ __forceinline__ void cp_async16(uint32_t saddr, const void* gptr) {
    asm volatile("cp.async.cg.shared.global [%0], [%1], 16;" :: "r"(saddr), "l"(gptr));
}
#define CP_COMMIT() asm volatile("cp.async.commit_group;")
#define CP_WAIT(n)  asm volatile("cp.async.wait_group %0;" :: "n"(n))

#define MMA_F16(d0,d1,d2,d3,a0,a1,a2,a3,b0,b1) \
    asm volatile( \
        "mma.sync.aligned.m16n8k16.row.col.f32.f16.f16.f32 " \
        "{%0,%1,%2,%3}, {%4,%5,%6,%7}, {%8,%9}, {%0,%1,%2,%3};" \
        : "+f"(d0), "+f"(d1), "+f"(d2), "+f"(d3) \
        : "r"(a0), "r"(a1), "r"(a2), "r"(a3), "r"(b0), "r"(b1))

__device__ __forceinline__ uint32_t packh2(float a, float b) {
    __half2 t = __floats2half2_rn(a, b);
    return *(uint32_t*)&t;
}

// ---------------------------------------------------------------------------
// Scratch (static device globals)
// ---------------------------------------------------------------------------
__device__ float  g_qdt  [T_SEQ * Q_LORA];
__device__ float  g_qcat [T_SEQ * QCAT];
__device__ float  g_kvd  [T_SEQ * KVD_PAD];
__device__ float  g_kvup [T_SEQ * N_HEADS * (NOPE + V_DIM)];

// fp16 operands
__device__ __half g_x16 [T_SEQ * DIM];
__device__ __half g_ql16[T_SEQ * Q_LORA];
__device__ __half g_ck16[T_SEQ * KV_LORA];
__device__ __half g_of16[T_SEQ * N_HEADS * V_DIM];
__device__ __half g_qh  [T_SEQ * N_HEADS * HD];
__device__ __half g_kh  [T_SEQ * N_HEADS * HD];
__device__ __half g_vt  [N_HEADS * V_DIM * T_SEQ];

// fp16 transposed (K-major [N][K]) weights
__device__ __half g_wqdT[Q_LORA * DIM];
__device__ __half g_wqT [QCAT * Q_LORA];
__device__ __half g_wkdT[KVD_PAD * DIM];
__device__ __half g_wkuT[(N_HEADS * (NOPE + V_DIM)) * KV_LORA];
__device__ __half g_woT [DIM * (N_HEADS * V_DIM)];

// ---------------------------------------------------------------------------
// fp32 -> fp16 convert (vectorized)
// ---------------------------------------------------------------------------
__global__ __launch_bounds__(256)
void convert_f16(const float* __restrict__ src, __half* __restrict__ dst, int n4) {
    int i = blockIdx.x * 256 + threadIdx.x;
    if (i < n4) {
        float4 v = *(const float4*)&src[i * 4];
        __half2* d = (__half2*)dst;
        d[i * 2]     = __floats2half2_rn(v.x, v.y);
        d[i * 2 + 1] = __floats2half2_rn(v.z, v.w);
    }
}

// ---------------------------------------------------------------------------
// Weight transpose: src[K][N] -> dst[NP][K] fp16, zero pad
// ---------------------------------------------------------------------------
__global__ __launch_bounds__(256)
void transpose_f16(const float* __restrict__ src, __half* __restrict__ dst,
                   int K, int N, int NP) {
    __shared__ float tile[32][33];
    int kb = blockIdx.y * 32, nb = blockIdx.x * 32;
    for (int i = threadIdx.y; i < 32; i += 8) {
        int n = nb + threadIdx.x;
        float v = (n < N) ? src[(size_t)(kb + i) * N + n] : 0.f;
        tile[i][threadIdx.x] = v;
    }
    __syncthreads();
    for (int i = threadIdx.y; i < 32; i += 8) {
        int n = nb + i;
        if (n < NP)
            dst[(size_t)n * K + kb + threadIdx.x] = __float2half_rn(tile[threadIdx.x][i]);
    }
}

// ---------------------------------------------------------------------------
// FP16 mma.sync GEMM (R12-exact, best measured)
// ---------------------------------------------------------------------------
#define HSMS 40
#define STAGES 3
#define HTILE (128 * HSMS)
#define GEMM_SMEM (STAGES * 2 * HTILE * 2)

__global__ __launch_bounds__(128)
void mma_gemm_f16(const __half* __restrict__ A, const __half* __restrict__ Bt,
                  float* __restrict__ C, int M, int N, int K) {
    extern __shared__ __half shh[];
    __half* AsAll = shh;
    __half* BsAll = shh + STAGES * HTILE;
    const uint32_t as_base = smem_u32(AsAll);
    const uint32_t bs_base = smem_u32(BsAll);

    const int tid  = threadIdx.x;
    const int wid  = tid >> 5, lane = tid & 31;
    const int gid  = lane >> 2, tig = lane & 3;
    const int wm   = wid >> 1, wn = wid & 1;
    const int bm   = blockIdx.y, bn = blockIdx.x;

    const __half* Ab = A  + (size_t)bm * 128 * K;
    const __half* Bb = Bt + (size_t)bn * 128 * K;

    const int lrow = tid >> 2;
    const int lc4  = tid & 3;

    float acc[4][8][4];
    #pragma unroll
    for (int i = 0; i < 4; i++)
        #pragma unroll
        for (int j = 0; j < 8; j++)
            #pragma unroll
            for (int k = 0; k < 4; k++) acc[i][j][k] = 0.f;

    const int nk = K >> 5;

    #pragma unroll
    for (int s = 0; s < STAGES - 1; s++) {
        const int k0 = s * 32;
        #pragma unroll
        for (int l = 0; l < 4; l++) {
            int row = lrow + l * 32;
            uint32_t soff = (uint32_t)(s * HTILE + row * HSMS) * 2 + lc4 * 16;
            cp_async16(as_base + soff, Ab + (size_t)row * K + k0 + lc4 * 8);
            cp_async16(bs_base + soff, Bb + (size_t)row * K + k0 + lc4 * 8);
        }
        CP_COMMIT();
    }

    for (int kt = 0; kt < nk; kt++) {
        CP_WAIT(STAGES - 2);
        __syncthreads();

        if (kt + STAGES - 1 < nk) {
            const int s = (kt + STAGES - 1) % STAGES;
            const int k0 = (kt + STAGES - 1) * 32;
            #pragma unroll
            for (int l = 0; l < 4; l++) {
                int row = lrow + l * 32;
                uint32_t soff = (uint32_t)(s * HTILE + row * HSMS) * 2 + lc4 * 16;
                cp_async16(as_base + soff, Ab + (size_t)row * K + k0 + lc4 * 8);
                cp_async16(bs_base + soff, Bb + (size_t)row * K + k0 + lc4 * 8);
            }
        }
        CP_COMMIT();

        const uint32_t* as = (const uint32_t*)(AsAll + (kt % STAGES) * HTILE);
        const uint32_t* bs = (const uint32_t*)(BsAll + (kt % STAGES) * HTILE);
        #pragma unroll
        for (int kc = 0; kc < 2; kc++) {
            const int kw = kc * 8 + tig;
            uint32_t a[4][4], b[8][2];
            #pragma unroll
            for (int mf = 0; mf < 4; mf++) {
                int row = wm * 64 + mf * 16 + gid;
                a[mf][0] = as[row * 20 + kw];
                a[mf][1] = as[(row + 8) * 20 + kw];
                a[mf][2] = as[row * 20 + kw + 4];
                a[mf][3] = as[(row + 8) * 20 + kw + 4];
            }
            #pragma unroll
            for (int nf = 0; nf < 8; nf++) {
                int col = wn * 64 + nf * 8 + gid;
                b[nf][0] = bs[col * 20 + kw];
                b[nf][1] = bs[col * 20 + kw + 4];
            }
            #pragma unroll
            for (int mf = 0; mf < 4; mf++)
                #pragma unroll
                for (int nf = 0; nf < 8; nf++)
                    MMA_F16(acc[mf][nf][0], acc[mf][nf][1], acc[mf][nf][2], acc[mf][nf][3],
                            a[mf][0], a[mf][1], a[mf][2], a[mf][3],
                            b[nf][0], b[nf][1]);
        }
    }

    #pragma unroll
    for (int mf = 0; mf < 4; mf++) {
        int row0 = bm * 128 + wm * 64 + mf * 16 + gid;
        #pragma unroll
        for (int nf = 0; nf < 8; nf++) {
            int col = bn * 128 + wn * 64 + nf * 8 + tig * 2;
            *(float2*)&C[(size_t)row0 * N + col]       = make_float2(acc[mf][nf][0], acc[mf][nf][1]);
            *(float2*)&C[(size_t)(row0 + 8) * N + col] = make_float2(acc[mf][nf][2], acc[mf][nf][3]);
        }
    }
}

// ---------------------------------------------------------------------------
// Row-wise RMSNorm, fp16 output
// ---------------------------------------------------------------------------
__global__ __launch_bounds__(256)
void rmsnorm_f16(const float* __restrict__ in, const float* __restrict__ w,
                 __half* __restrict__ out, int instride, int outstride, int cols) {
    int r = blockIdx.x;
    const float* row = in + (size_t)r * instride;
    float ss = 0.f;
    for (int c = threadIdx.x; c < cols; c += blockDim.x) {
        float v = row[c];
        ss += v * v;
    }
    __shared__ float red[8];
    int lane = threadIdx.x & 31, wid = threadIdx.x >> 5;
    #pragma unroll
    for (int o = 16; o; o >>= 1) ss += __shfl_xor_sync(0xFFFFFFFFu, ss, o);
    if (lane == 0) red[wid] = ss;
    __syncthreads();
    if (wid == 0) {
        float v = (lane < 8) ? red[lane] : 0.f;
        #pragma unroll
        for (int o = 4; o; o >>= 1) v += __shfl_xor_sync(0xFFFFFFFFu, v, o);
        if (lane == 0) red[0] = v;
    }
    __syncthreads();
    float inv = rsqrtf(red[0] / (float)cols + EPS);
    __half* orow = out + (size_t)r * outstride;
    for (int c = threadIdx.x; c < cols; c += blockDim.x)
        orow[c] = __float2half_rn(row[c] * inv * w[c]);
}

// ---------------------------------------------------------------------------
// Assemble Q -> fp16 g_qh from concatenated q projection
// ---------------------------------------------------------------------------
__global__ __launch_bounds__(256)
void assemble_q(const float* __restrict__ freqs) {
    int t = blockIdx.x;
    int tid = threadIdx.x;
    for (int i = tid; i < 512; i += 256) {
        int e = i * 4;
        int h = e >> 7, d = e & 127;
        float4 v = *(const float4*)&g_qcat[(size_t)t * QCAT + e];
        __half* dst = &g_qh[((size_t)t * N_HEADS + h) * HD + d];
        *(__half2*)&dst[0] = __floats2half2_rn(v.x, v.y);
        *(__half2*)&dst[2] = __floats2half2_rn(v.z, v.w);
    }
    for (int i = tid; i < N_HEADS * 32; i += 256) {
        int h = i >> 5, p = i & 31;
        float f = freqs[t * 32 + p];
        float c = cosf(f), s = sinf(f);
        const float* src = &g_qcat[(size_t)t * QCAT + N_HEADS * NOPE + h * ROPE + 2 * p];
        float x1 = src[0], x2 = src[1];
        __half* dst = &g_qh[((size_t)t * N_HEADS + h) * HD + NOPE + 2 * p];
        *(__half2*)dst = __floats2half2_rn(x1 * c - x2 * s, x1 * s + x2 * c);
    }
}

// ---------------------------------------------------------------------------
// Assemble K -> fp16 g_kh
// ---------------------------------------------------------------------------
__global__ __launch_bounds__(256)
void assemble_k(const float* __restrict__ freqs) {
    int t = blockIdx.x;
    int tid = threadIdx.x;
    for (int i = tid; i < 512; i += 256) {
        int e = i * 4;
        int h = e >> 7, d = e & 127;
        float4 v = *(const float4*)&g_kvup[(size_t)t * (N_HEADS * (NOPE + V_DIM)) + h * (NOPE + V_DIM) + d];
        __half* dst = &g_kh[((size_t)t * N_HEADS + h) * HD + d];
        *(__half2*)&dst[0] = __floats2half2_rn(v.x, v.y);
        *(__half2*)&dst[2] = __floats2half2_rn(v.z, v.w);
    }
    __shared__ __half2 rk[32];
    if (tid < 32) {
        float f = freqs[t * 32 + tid];
        float c = cosf(f), s = sinf(f);
        const float* src = &g_kvd[(size_t)t * KVD_PAD + KV_LORA + 2 * tid];
        float x1 = src[0], x2 = src[1];
        rk[tid] = __floats2half2_rn(x1 * c - x2 * s, x1 * s + x2 * c);
    }
    __syncthreads();
    for (int i = tid; i < N_HEADS * 32; i += 256) {
        int h = i >> 5, p = i & 31;
        *(__half2*)&g_kh[((size_t)t * N_HEADS + h) * HD + NOPE + 2 * p] = rk[p];
    }
}

// ---------------------------------------------------------------------------
// V transpose: g_kvup V-part -> g_vt[h][d][t] fp16
// ---------------------------------------------------------------------------
__global__ __launch_bounds__(256)
void transpose_v() {
    __shared__ __half tile[32][33];
    int h = blockIdx.z;
    int t0 = blockIdx.x * 32, d0 = blockIdx.y * 32;
    for (int i = threadIdx.y; i < 32; i += 8) {
        int t = t0 + i, d = d0 + threadIdx.x;
        tile[i][threadIdx.x] = __float2half_rn(
            g_kvup[(size_t)t * (N_HEADS * (NOPE + V_DIM)) + h * (NOPE + V_DIM) + NOPE + d]);
    }
    __syncthreads();
    for (int i = threadIdx.y; i < 32; i += 8) {
        int d = d0 + i;
        g_vt[((size_t)h * V_DIM + d) * T_SEQ + t0 + threadIdx.x] = tile[threadIdx.x][i];
    }
}

// ---------------------------------------------------------------------------
// FlashAttention-2 causal attention (R15 math; K/V tile loads via cp.async)
// ---------------------------------------------------------------------------
#define AQS 200
#define AVS 72
#define SMEM_FA ((64 * AQS + 64 * AQS + 128 * AVS) * 2)

__global__ __launch_bounds__(128, 3)
void attn_fa2() {
    extern __shared__ __half smh[];
    __half* Qh = smh;
    __half* Kh = Qh + 64 * AQS;
    __half* Vt = Kh + 64 * AQS;
    const uint32_t* Qw = (const uint32_t*)Qh;
    const uint32_t* Kw = (const uint32_t*)Kh;
    const uint32_t* Vw = (const uint32_t*)Vt;
    const uint32_t kh_base = smem_u32(Kh);
    const uint32_t vt_base = smem_u32(Vt);

    const int h  = blockIdx.y;
    const int qt = blockIdx.x;
    const int tid = threadIdx.x;
    const int w = tid >> 5, lane = tid & 31;
    const int gid = lane >> 2, tig = lane & 3;
    const int q0 = qt * 64;
    const float scale = 0.07216878364870323f;

    for (int i = tid; i < 1536; i += 128) {
        int r = i / 24, c = i % 24;
        *(uint4*)(Qh + r * AQS + c * 8) =
            *(const uint4*)(g_qh + ((size_t)(q0 + r) * N_HEADS + h) * HD + c * 8);
    }

    float o[16][4];
    #pragma unroll
    for (int nf = 0; nf < 16; nf++) {
        o[nf][0] = 0.f; o[nf][1] = 0.f; o[nf][2] = 0.f; o[nf][3] = 0.f;
    }
    float m0 = -1e30f, m1 = -1e30f, l0 = 0.f, l1 = 0.f;
    const int row0 = w * 16 + gid;

    const int ntiles = qt + 1;
    for (int kt = 0; kt < ntiles; kt++) {
        __syncthreads();
        // K/V tile loads via cp.async (no register round-trip)
        #pragma unroll
        for (int l = 0; l < 12; l++) {
            int i = tid + l * 128;
            int r = i / 24, c = i % 24;
            cp_async16(kh_base + (uint32_t)(r * AQS + c * 8) * 2,
                       g_kh + ((size_t)(kt * 64 + r) * N_HEADS + h) * HD + c * 8);
        }
        #pragma unroll
        for (int l = 0; l < 8; l++) {
            int i = tid + l * 128;
            int d = i >> 3, c = i & 7;
            cp_async16(vt_base + (uint32_t)(d * AVS + c * 8) * 2,
                       g_vt + ((size_t)h * V_DIM + d) * T_SEQ + kt * 64 + c * 8);
        }
        CP_COMMIT();
        CP_WAIT(0);
        __syncthreads();

        float s[8][4];
        #pragma unroll
        for (int nf = 0; nf < 8; nf++) {
            s[nf][0] = 0.f; s[nf][1] = 0.f; s[nf][2] = 0.f; s[nf][3] = 0.f;
        }
        #pragma unroll
        for (int kc = 0; kc < 12; kc++) {
            uint32_t a0 = Qw[row0 * 100 + kc * 8 + tig];
            uint32_t a1 = Qw[(row0 + 8) * 100 + kc * 8 + tig];
            uint32_t a2 = Qw[row0 * 100 + kc * 8 + tig + 4];
            uint32_t a3 = Qw[(row0 + 8) * 100 + kc * 8 + tig + 4];
            #pragma unroll
            for (int nf = 0; nf < 8; nf++) {
                int col = nf * 8 + gid;
                uint32_t b0 = Kw[col * 100 + kc * 8 + tig];
                uint32_t b1 = Kw[col * 100 + kc * 8 + tig + 4];
                MMA_F16(s[nf][0], s[nf][1], s[nf][2], s[nf][3],
                        a0, a1, a2, a3, b0, b1);
            }
        }

        const int qg0 = q0 + row0, qg1 = qg0 + 8;
        #pragma unroll
        for (int nf = 0; nf < 8; nf++) {
            int jg = kt * 64 + nf * 8 + tig * 2;
            s[nf][0] = (jg     <= qg0) ? s[nf][0] * scale : -1e30f;
            s[nf][1] = (jg + 1 <= qg0) ? s[nf][1] * scale : -1e30f;
            s[nf][2] = (jg     <= qg1) ? s[nf][2] * scale : -1e30f;
            s[nf][3] = (jg + 1 <= qg1) ? s[nf][3] * scale : -1e30f;
        }

        float rm0 = -1e30f, rm1 = -1e30f;
        #pragma unroll
        for (int nf = 0; nf < 8; nf++) {
            rm0 = fmaxf(rm0, fmaxf(s[nf][0], s[nf][1]));
            rm1 = fmaxf(rm1, fmaxf(s[nf][2], s[nf][3]));
        }
        rm0 = fmaxf(rm0, __shfl_xor_sync(0xFFFFFFFFu, rm0, 1));
        rm0 = fmaxf(rm0, __shfl_xor_sync(0xFFFFFFFFu, rm0, 2));
        rm1 = fmaxf(rm1, __shfl_xor_sync(0xFFFFFFFFu, rm1, 1));
        rm1 = fmaxf(rm1, __shfl_xor_sync(0xFFFFFFFFu, rm1, 2));
        float nm0 = fmaxf(m0, rm0), nm1 = fmaxf(m1, rm1);
        float sc0 = __expf(m0 - nm0), sc1 = __expf(m1 - nm1);
        m0 = nm0; m1 = nm1;
        float rs0 = 0.f, rs1 = 0.f;
        #pragma unroll
        for (int nf = 0; nf < 8; nf++) {
            s[nf][0] = __expf(s[nf][0] - nm0); rs0 += s[nf][0];
            s[nf][1] = __expf(s[nf][1] - nm0); rs0 += s[nf][1];
            s[nf][2] = __expf(s[nf][2] - nm1); rs1 += s[nf][2];
            s[nf][3] = __expf(s[nf][3] - nm1); rs1 += s[nf][3];
        }
        rs0 += __shfl_xor_sync(0xFFFFFFFFu, rs0, 1);
        rs0 += __shfl_xor_sync(0xFFFFFFFFu, rs0, 2);
        rs1 += __shfl_xor_sync(0xFFFFFFFFu, rs1, 1);
        rs1 += __shfl_xor_sync(0xFFFFFFFFu, rs1, 2);
        l0 = l0 * sc0 + rs0;
        l1 = l1 * sc1 + rs1;
        #pragma unroll
        for (int nf = 0; nf < 16; nf++) {
            o[nf][0] *= sc0; o[nf][1] *= sc0;
            o[nf][2] *= sc1; o[nf][3] *= sc1;
        }

        #pragma unroll
        for (int kc = 0; kc < 4; kc++) {
            uint32_t a0 = packh2(s[2 * kc][0],     s[2 * kc][1]);
            uint32_t a1 = packh2(s[2 * kc][2],     s[2 * kc][3]);
            uint32_t a2 = packh2(s[2 * kc + 1][0], s[2 * kc + 1][1]);
            uint32_t a3 = packh2(s[2 * kc + 1][2], s[2 * kc + 1][3]);
            #pragma unroll
            for (int nf = 0; nf < 16; nf++) {
                int n = nf * 8 + gid;
                uint32_t b0 = Vw[n * 36 + kc * 8 + tig];
                uint32_t b1 = Vw[n * 36 + kc * 8 + tig + 4];
                MMA_F16(o[nf][0], o[nf][1], o[nf][2], o[nf][3],
                        a0, a1, a2, a3, b0, b1);
            }
        }
    }

    float li0 = 1.f / l0, li1 = 1.f / l1;
    const int gr0 = q0 + row0, gr1 = gr0 + 8;
    #pragma unroll
    for (int nf = 0; nf < 16; nf++) {
        int col = nf * 8 + tig * 2;
        *(__half2*)&g_of16[(size_t)gr0 * (N_HEADS * V_DIM) + h * V_DIM + col] =
            __floats2half2_rn(o[nf][0] * li0, o[nf][1] * li0);
        *(__half2*)&g_of16[(size_t)gr1 * (N_HEADS * V_DIM) + h * V_DIM + col] =
            __floats2half2_rn(o[nf][2] * li1, o[nf][3] * li1);
    }
}

// ---------------------------------------------------------------------------
// Launcher (R15 dual-stream exact)
// ---------------------------------------------------------------------------
extern "C" void kernel_launch(void* const* d_in, const int* in_sizes, int n_in,
                              void* d_out, int out_size) {
    const float* x         = (const float*)d_in[0];
    const float* freqs     = (const float*)d_in[1];
    const float* wq_down   = (const float*)d_in[3];
    const float* q_norm_w  = (const float*)d_in[4];
    const float* wq_nope   = (const float*)d_in[5];
    const float* wq_rope   = (const float*)d_in[6];
    const float* wkv_down  = (const float*)d_in[7];
    const float* kv_norm_w = (const float*)d_in[8];
    const float* wkv_up    = (const float*)d_in[9];
    const float* wo        = (const float*)d_in[10];
    float* out = (float*)d_out;

    float *p_qdt, *p_qcat, *p_kvd, *p_kvup;
    __half *p_x16, *p_ql16, *p_ck16, *p_of16;
    __half *p_wqdT, *p_wqT, *p_wkdT, *p_wkuT, *p_woT;
    cudaGetSymbolAddress((void**)&p_qdt,   g_qdt);
    cudaGetSymbolAddress((void**)&p_qcat,  g_qcat);
    cudaGetSymbolAddress((void**)&p_kvd,   g_kvd);
    cudaGetSymbolAddress((void**)&p_kvup,  g_kvup);
    cudaGetSymbolAddress((void**)&p_x16,   g_x16);
    cudaGetSymbolAddress((void**)&p_ql16,  g_ql16);
    cudaGetSymbolAddress((void**)&p_ck16,  g_ck16);
    cudaGetSymbolAddress((void**)&p_of16,  g_of16);
    cudaGetSymbolAddress((void**)&p_wqdT,  g_wqdT);
    cudaGetSymbolAddress((void**)&p_wqT,   g_wqT);
    cudaGetSymbolAddress((void**)&p_wkdT,  g_wkdT);
    cudaGetSymbolAddress((void**)&p_wkuT,  g_wkuT);
    cudaGetSymbolAddress((void**)&p_woT,   g_woT);

    cudaFuncSetAttribute(mma_gemm_f16, cudaFuncAttributeMaxDynamicSharedMemorySize, GEMM_SMEM);
    cudaFuncSetAttribute(attn_fa2, cudaFuncAttributeMaxDynamicSharedMemorySize, SMEM_FA);

    static cudaStream_t s1 = nullptr;
    static cudaEvent_t  ev_x = nullptr, ev_kv = nullptr;
    if (!s1) {
        cudaStreamCreateWithFlags(&s1, cudaStreamNonBlocking);
        cudaEventCreateWithFlags(&ev_x,  cudaEventDisableTiming);
        cudaEventCreateWithFlags(&ev_kv, cudaEventDisableTiming);
    }
    cudaStream_t s0 = 0;

    const dim3 tb(32, 8);
    const int MB = T_SEQ / 128;   // 24

    convert_f16<<<(T_SEQ * DIM / 4 + 255) / 256, 256, 0, s0>>>(x, p_x16, T_SEQ * DIM / 4);
    cudaEventRecord(ev_x, s0);

    cudaStreamWaitEvent(s1, ev_x, 0);
    transpose_f16<<<dim3(KVD_PAD / 32, DIM / 32), tb, 0, s1>>>(wkv_down, p_wkdT, DIM, KV_LORA + ROPE, KVD_PAD);
    mma_gemm_f16<<<dim3(KVD_PAD / 128, MB), 128, GEMM_SMEM, s1>>>(p_x16, p_wkdT, p_kvd, T_SEQ, KVD_PAD, DIM);
    transpose_f16<<<dim3((N_HEADS*(NOPE+V_DIM)) / 32, KV_LORA / 32), tb, 0, s1>>>(wkv_up, p_wkuT, KV_LORA, N_HEADS*(NOPE+V_DIM), N_HEADS*(NOPE+V_DIM));
    rmsnorm_f16<<<T_SEQ, 256, 0, s1>>>(p_kvd, kv_norm_w, p_ck16, KVD_PAD, KV_LORA, KV_LORA);
    mma_gemm_f16<<<dim3((N_HEADS*(NOPE+V_DIM)) / 128, MB), 128, GEMM_SMEM, s1>>>(p_ck16, p_wkuT, p_kvup, T_SEQ, N_HEADS*(NOPE+V_DIM), KV_LORA);
    assemble_k<<<T_SEQ, 256, 0, s1>>>(freqs);
    transpose_v<<<dim3(T_SEQ / 32, V_DIM / 32, N_HEADS), tb, 0, s1>>>();
    cudaEventRecord(ev_kv, s1);

    transpose_f16<<<dim3(Q_LORA / 32, DIM / 32), tb, 0, s0>>>(wq_down, p_wqdT, DIM, Q_LORA, Q_LORA);
    mma_gemm_f16<<<dim3(Q_LORA / 128, MB), 128, GEMM_SMEM, s0>>>(p_x16, p_wqdT, p_qdt, T_SEQ, Q_LORA, DIM);
    transpose_f16<<<dim3((N_HEADS*NOPE) / 32, Q_LORA / 32), tb, 0, s0>>>(wq_nope, p_wqT, Q_LORA, N_HEADS*NOPE, N_HEADS*NOPE);
    transpose_f16<<<dim3((N_HEADS*ROPE) / 32, Q_LORA / 32), tb, 0, s0>>>(wq_rope, p_wqT + (size_t)(N_HEADS*NOPE) * Q_LORA, Q_LORA, N_HEADS*ROPE, N_HEADS*ROPE);
    transpose_f16<<<dim3(DIM / 32, (N_HEADS*V_DIM) / 32), tb, 0, s0>>>(wo, p_woT, N_HEADS*V_DIM, DIM, DIM);
    rmsnorm_f16<<<T_SEQ, 256, 0, s0>>>(p_qdt, q_norm_w, p_ql16, Q_LORA, Q_LORA, Q_LORA);
    mma_gemm_f16<<<dim3(QCAT / 128, MB), 128, GEMM_SMEM, s0>>>(p_ql16, p_wqT, p_qcat, T_SEQ, QCAT, Q_LORA);
    assemble_q<<<T_SEQ, 256, 0, s0>>>(freqs);

    cudaStreamWaitEvent(s0, ev_kv, 0);
    attn_fa2<<<dim3(T_SEQ / 64, N_HEADS), 128, SMEM_FA, s0>>>();
    mma_gemm_f16<<<dim3(DIM / 128, MB), 128, GEMM_SMEM, s0>>>(p_of16, p_woT, out, T_SEQ, DIM, DIM);
}